// round 4
// baseline (speedup 1.0000x reference)
#include <cuda_runtime.h>

#define NLAYERS 10
#define HID     100
#define HPAD    112
#define BATCH   512
#define TSTEPS  512
#define NCHUNK  16
#define CHUNKB  32
#define RING_D  8
#define NSTAGES 9          // stage0 = layers {0,1}; stage s>=1 = layer s+1
#define NTHREADS 512
#define NWARPS   16
#define JPW      7         // 16*7 = 112 >= 100

// ---- shared memory layout (floats) ----
#define OFF_W0   0                      // stage0: Whh[0];  stage s: Wih[s]
#define OFF_W1   (OFF_W0 + HPAD*HID)    // stage0: Wih[0];  stage s: Whh[s+1]
#define OFF_W2   (OFF_W1 + HPAD*HID)    // stage0 only: Whh[1]
#define OFF_BA   (OFF_W2 + HPAD*HID)    // stage0: bias L0; stage s: bias l
#define OFF_BB   (OFF_BA + HPAD)        // stage0: bias L1
#define OFF_AUX  (OFF_BB + HPAD)        // stage0: Wi0;  stage8: Wout
#define OFF_HA   (OFF_AUX + HPAD)       // [2][CHUNKB*HID] hidden (stage0: L0)
#define OFF_HB   (OFF_HA + 2*CHUNKB*HID)// stage0: [2] hidden L1; stage>=1: [0]=sInp
#define OFF_RED  (OFF_HB + 2*CHUNKB*HID)
#define OFF_SC   (OFF_RED + NWARPS*32)
#define SMEM_FLOATS (OFF_SC + 4)

// ---- global scratch: activation rings + flags ----
#define NPAIRS ((NSTAGES-1)*NCHUNK)     // 128
__device__ float    g_ring[(size_t)NPAIRS * RING_D * CHUNKB * HID];
__device__ unsigned g_prod[NPAIRS];
__device__ unsigned g_cons[NPAIRS];

__device__ __forceinline__ unsigned ld_acq(const unsigned* p) {
    unsigned v;
    asm volatile("ld.acquire.gpu.global.u32 %0, [%1];" : "=r"(v) : "l"(p) : "memory");
    return v;
}
__device__ __forceinline__ void st_rel(unsigned* p, unsigned v) {
    asm volatile("st.release.gpu.global.u32 [%0], %1;" :: "l"(p), "r"(v) : "memory");
}
__device__ __forceinline__ unsigned long long ffma2(unsigned long long a,
                                                    unsigned long long b,
                                                    unsigned long long c) {
    unsigned long long d;
    asm("fma.rn.f32x2 %0, %1, %2, %3;" : "=l"(d) : "l"(a), "l"(b), "l"(c));
    return d;
}
__device__ __forceinline__ unsigned long long pack2(float lo, float hi) {
    unsigned long long r;
    asm("mov.b64 %0, {%1, %2};" : "=l"(r) : "f"(lo), "f"(hi));
    return r;
}
__device__ __forceinline__ float hsum2(unsigned long long v) {
    float a, b;
    asm("mov.b64 {%0, %1}, %2;" : "=f"(a), "=f"(b) : "l"(v));
    return a + b;
}

__global__ void rnn_reset_kernel() {
    int i = threadIdx.x;
    if (i < NPAIRS) { g_prod[i] = 0u; g_cons[i] = 0u; }
}

// dual-matrix accumulate: tanh(bias + Wi*in + Wh*h) for JPW j's of this warp
__device__ __forceinline__ void mm_dual(const float* __restrict__ Wi,
                                        const float* __restrict__ Wh,
                                        const float* __restrict__ irow,
                                        const float* __restrict__ hrow,
                                        const float* __restrict__ bias,
                                        int jbase, float* hn) {
    unsigned long long acc[JPW];
#pragma unroll
    for (int i = 0; i < JPW; i++) acc[i] = pack2(bias[jbase + i], 0.f);
    for (int k = 0; k < HID; k += 4) {
        ulonglong2 in2 = *(const ulonglong2*)(irow + k);
        ulonglong2 h2  = *(const ulonglong2*)(hrow + k);
#pragma unroll
        for (int i = 0; i < JPW; i++) {
            ulonglong2 wi2 = *(const ulonglong2*)(Wi + (jbase + i) * HID + k);
            ulonglong2 wh2 = *(const ulonglong2*)(Wh + (jbase + i) * HID + k);
            acc[i] = ffma2(in2.x, wi2.x, acc[i]);
            acc[i] = ffma2(in2.y, wi2.y, acc[i]);
            acc[i] = ffma2(h2.x,  wh2.x, acc[i]);
            acc[i] = ffma2(h2.y,  wh2.y, acc[i]);
        }
    }
#pragma unroll
    for (int i = 0; i < JPW; i++) hn[i] = tanhf(hsum2(acc[i]));
}

// single-matrix (layer 0): tanh(bias + x*Wi0 + Wh*h)
__device__ __forceinline__ void mm_single(const float* __restrict__ Wh,
                                          const float* __restrict__ hrow,
                                          const float* __restrict__ bias,
                                          const float* __restrict__ aux,
                                          float xv, int jbase, float* hn) {
    unsigned long long acc[JPW];
#pragma unroll
    for (int i = 0; i < JPW; i++)
        acc[i] = pack2(bias[jbase + i] + xv * aux[jbase + i], 0.f);
    for (int k = 0; k < HID; k += 4) {
        ulonglong2 h2 = *(const ulonglong2*)(hrow + k);
#pragma unroll
        for (int i = 0; i < JPW; i++) {
            ulonglong2 wh2 = *(const ulonglong2*)(Wh + (jbase + i) * HID + k);
            acc[i] = ffma2(h2.x, wh2.x, acc[i]);
            acc[i] = ffma2(h2.y, wh2.y, acc[i]);
        }
    }
#pragma unroll
    for (int i = 0; i < JPW; i++) hn[i] = tanhf(hsum2(acc[i]));
}

__global__ __launch_bounds__(NTHREADS)
void rnn_kernel(const float* __restrict__ x,      // [B, T, 1]
                const float* __restrict__ h0,     // [L, B, H]
                const float* __restrict__ Wi0,    // [H, 1]
                const float* __restrict__ Wih,    // [L-1, H, H]
                const float* __restrict__ Whh,    // [L, H, H]
                const float* __restrict__ bih,    // [L, H]
                const float* __restrict__ bhh,    // [L, H]
                const float* __restrict__ Wout,   // [1, H]
                const float* __restrict__ bout,   // [1]
                float* __restrict__ out)          // [B*T] outs ++ [L*B*H] h_final
{
    extern __shared__ float sm[];
    float* sW0   = sm + OFF_W0;
    float* sW1   = sm + OFF_W1;
    float* sW2   = sm + OFF_W2;
    float* sBA   = sm + OFF_BA;
    float* sBB   = sm + OFF_BB;
    float* sAux  = sm + OFF_AUX;
    float* sHA   = sm + OFF_HA;   // [2][CHUNKB*HID]
    float* sHB   = sm + OFF_HB;   // [2][CHUNKB*HID] (stage>=1: [0] is sInp)
    float* sRed  = sm + OFF_RED;
    float* sSC   = sm + OFF_SC;

    const int tid   = threadIdx.x;
    const int warp  = tid >> 5;
    const int lane  = tid & 31;
    const int stage = blockIdx.x / NCHUNK;
    const int chunk = blockIdx.x % NCHUNK;
    const int b0    = chunk * CHUNKB;
    const int jbase = warp * JPW;

    // ---------------- init smem ----------------
    {
        if (stage == 0) {
            const float* gW0 = Whh;                         // layer 0 Whh
            const float* gW1 = Wih;                         // layer 1 Wih (= Wih[0])
            const float* gW2 = Whh + (size_t)HID * HID;     // layer 1 Whh
            for (int idx = tid; idx < HPAD * HID; idx += NTHREADS) {
                int j = idx / HID;
                bool v = j < HID;
                sW0[idx] = v ? gW0[idx] : 0.f;
                sW1[idx] = v ? gW1[idx] : 0.f;
                sW2[idx] = v ? gW2[idx] : 0.f;
            }
            for (int idx = tid; idx < HPAD; idx += NTHREADS) {
                bool v = idx < HID;
                sBA[idx]  = v ? (bih[idx] + bhh[idx]) : 0.f;
                sBB[idx]  = v ? (bih[HID + idx] + bhh[HID + idx]) : 0.f;
                sAux[idx] = v ? Wi0[idx] : 0.f;
            }
            const float* gh0 = h0 + (size_t)b0 * HID;                       // layer 0
            const float* gh1 = h0 + (size_t)BATCH * HID + (size_t)b0 * HID; // layer 1
            for (int idx = tid; idx < CHUNKB * HID; idx += NTHREADS) {
                sHA[idx] = gh0[idx];
                sHB[idx] = gh1[idx];
            }
        } else {
            const int l = stage + 1;
            const float* gW0 = Wih + (size_t)(l - 1) * HID * HID;
            const float* gW1 = Whh + (size_t)l * HID * HID;
            for (int idx = tid; idx < HPAD * HID; idx += NTHREADS) {
                int j = idx / HID;
                bool v = j < HID;
                sW0[idx] = v ? gW0[idx] : 0.f;
                sW1[idx] = v ? gW1[idx] : 0.f;
            }
            for (int idx = tid; idx < HPAD; idx += NTHREADS) {
                bool v = idx < HID;
                sBA[idx]  = v ? (bih[l * HID + idx] + bhh[l * HID + idx]) : 0.f;
                sAux[idx] = (v && stage == NSTAGES - 1) ? Wout[idx] : 0.f;
            }
            const float* gh = h0 + (size_t)l * BATCH * HID + (size_t)b0 * HID;
            for (int idx = tid; idx < CHUNKB * HID; idx += NTHREADS) sHA[idx] = gh[idx];
        }
        if (tid == 0) sSC[0] = bout[0];
    }
    __syncthreads();

    const int pc_in  = (stage - 1) * NCHUNK + chunk;  // valid stage>=1
    const int pc_out = stage * NCHUNK + chunk;        // valid stage<8
    float* ring_in  = g_ring + (size_t)pc_in  * RING_D * CHUNKB * HID;
    float* ring_out = g_ring + (size_t)pc_out * RING_D * CHUNKB * HID;

    float hn[JPW];

    if (stage == 0) {
        float xv = x[(size_t)(b0 + lane) * TSTEPS];  // t=0 prefetched
        for (int t = 0; t < TSTEPS; t++) {
            const int cur = t & 1, nxt = cur ^ 1;
            float* hA_cur = sHA + cur * CHUNKB * HID;
            float* hA_nxt = sHA + nxt * CHUNKB * HID;
            float* hB_cur = sHB + cur * CHUNKB * HID;
            float* hB_nxt = sHB + nxt * CHUNKB * HID;

            // ---- layer 0 ----
            mm_single(sW0, hA_cur + lane * HID, sBA, sAux, xv, jbase, hn);
            if (t + 1 < TSTEPS) xv = x[(size_t)(b0 + lane) * TSTEPS + t + 1];
#pragma unroll
            for (int i = 0; i < JPW; i++) {
                int j = jbase + i;
                if (j < HID) hA_nxt[lane * HID + j] = hn[i];
            }
            if (tid == 0 && t >= RING_D) {
                unsigned need = (unsigned)(t + 1 - RING_D);
                while (ld_acq(&g_cons[pc_out]) < need) {}
            }
            __syncthreads();  // hA_nxt ready for layer 1; backpressure confirmed

            // ---- layer 1 ----
            mm_dual(sW1, sW2, hA_nxt + lane * HID, hB_cur + lane * HID, sBB, jbase, hn);
            float* slot = ring_out + (size_t)(t & (RING_D - 1)) * CHUNKB * HID;
#pragma unroll
            for (int i = 0; i < JPW; i++) {
                int j = jbase + i;
                if (j < HID) { hB_nxt[lane * HID + j] = hn[i]; slot[lane * HID + j] = hn[i]; }
            }
            __syncthreads();  // slot writes complete
            if (tid == 0) st_rel(&g_prod[pc_out], (unsigned)(t + 1));
        }
        // final hidden: layers 0 and 1 (buffer parity 512&1 = 0)
        float* hf0 = out + (size_t)BATCH * TSTEPS + (size_t)b0 * HID;
        float* hf1 = out + (size_t)BATCH * TSTEPS + (size_t)BATCH * HID + (size_t)b0 * HID;
        for (int idx = tid; idx < CHUNKB * HID; idx += NTHREADS) {
            hf0[idx] = sHA[idx];
            hf1[idx] = sHB[idx];
        }
    } else {
        const bool last = (stage == NSTAGES - 1);
        float* sInp = sHB;  // single buffer
        for (int t = 0; t < TSTEPS; t++) {
            const int cur = t & 1, nxt = cur ^ 1;
            float* hA_cur = sHA + cur * CHUNKB * HID;
            float* hA_nxt = sHA + nxt * CHUNKB * HID;

            if (tid == 0) {
                while (ld_acq(&g_prod[pc_in]) < (unsigned)(t + 1)) {}
                if (!last && t >= RING_D) {
                    unsigned need = (unsigned)(t + 1 - RING_D);
                    while (ld_acq(&g_cons[pc_out]) < need) {}
                }
            }
            __syncthreads();  // b1: input available, backpressure ok

            const float4* src = (const float4*)(ring_in + (size_t)(t & (RING_D - 1)) * CHUNKB * HID);
            float4* dst = (float4*)sInp;
#pragma unroll
            for (int i = tid; i < CHUNKB * HID / 4; i += NTHREADS) dst[i] = __ldcg(src + i);
            __syncthreads();  // b2: input staged
            if (tid == 0) st_rel(&g_cons[pc_in], (unsigned)(t + 1));

            mm_dual(sW0, sW1, sInp + lane * HID, hA_cur + lane * HID, sBA, jbase, hn);

            if (!last) {
                float* slot = ring_out + (size_t)(t & (RING_D - 1)) * CHUNKB * HID;
#pragma unroll
                for (int i = 0; i < JPW; i++) {
                    int j = jbase + i;
                    if (j < HID) { hA_nxt[lane * HID + j] = hn[i]; slot[lane * HID + j] = hn[i]; }
                }
                __syncthreads();  // b3
                if (tid == 0) st_rel(&g_prod[pc_out], (unsigned)(t + 1));
            } else {
                float part = 0.f;
#pragma unroll
                for (int i = 0; i < JPW; i++) {
                    int j = jbase + i;
                    if (j < HID) { hA_nxt[lane * HID + j] = hn[i]; part += hn[i] * sAux[j]; }
                }
                sRed[warp * 32 + lane] = part;
                __syncthreads();  // b3
                if (warp == 0) {
                    float s = sSC[0];
#pragma unroll
                    for (int w = 0; w < NWARPS; w++) s += sRed[w * 32 + lane];
                    out[(size_t)(b0 + lane) * TSTEPS + t] = s;
                }
            }
        }
        const int l = stage + 1;
        float* hf = out + (size_t)BATCH * TSTEPS + (size_t)l * BATCH * HID + (size_t)b0 * HID;
        __syncthreads();
        for (int idx = tid; idx < CHUNKB * HID; idx += NTHREADS) hf[idx] = sHA[idx];
    }
}

extern "C" void kernel_launch(void* const* d_in, const int* in_sizes, int n_in,
                              void* d_out, int out_size) {
    const float* x    = (const float*)d_in[0];
    const float* h0   = (const float*)d_in[1];
    const float* Wi0  = (const float*)d_in[2];
    const float* Wih  = (const float*)d_in[3];
    const float* Whh  = (const float*)d_in[4];
    const float* bih  = (const float*)d_in[5];
    const float* bhh  = (const float*)d_in[6];
    const float* Wout = (const float*)d_in[7];
    const float* bout = (const float*)d_in[8];
    float* out = (float*)d_out;

    cudaFuncSetAttribute(rnn_kernel, cudaFuncAttributeMaxDynamicSharedMemorySize,
                         SMEM_FLOATS * (int)sizeof(float));

    rnn_reset_kernel<<<1, 256>>>();
    rnn_kernel<<<NSTAGES * NCHUNK, NTHREADS, SMEM_FLOATS * sizeof(float)>>>(
        x, h0, Wi0, Wih, Whh, bih, bhh, Wout, bout, out);
}

// round 7
// speedup vs baseline: 1.8070x; 1.8070x over previous
#include <cuda_runtime.h>
#include <cuda_fp16.h>
#include <cstdint>

#define HID      100
#define BATCH    512
#define TSTEPS   512
#define NCHUNK   8
#define CHUNKB   64
#define NSTAGES  10
#define NTHREADS 256
#define RING_D   4
#define NPAIRS   ((NSTAGES-1)*NCHUNK)   // 72

#define SCALE_LO 2048.0f
#define INV_LO   (1.0f/2048.0f)

// ---- smem byte offsets ----
#define S_RED    0                       // 8*64*4 = 2048
#define S_BI_HI  2048                    // B input region  [64][128] f16 = 16KB
#define S_BI_LO  (S_BI_HI + 16384)
#define S_BH_HI  (S_BI_LO + 16384)       // B hidden region [64][128] f16
#define S_BH_LO  (S_BH_HI + 16384)
#define S_A_HI   (S_BH_LO + 16384)       // A staging [128][224] f16 = 57344
#define S_A_LO   (S_A_HI + 57344)
#define SMEM_BYTES (S_A_LO + 57344)      // 182272

#define RING_SLOT 32768
__device__ unsigned char g_ring[(size_t)NPAIRS * RING_D * RING_SLOT];
__device__ unsigned g_prod[NPAIRS];
__device__ unsigned g_cons[NPAIRS];

__device__ __forceinline__ uint32_t smem_u32(const void* p) {
    uint32_t a;
    asm("{ .reg .u64 t; cvta.to.shared.u64 t, %1; cvt.u32.u64 %0, t; }" : "=r"(a) : "l"(p));
    return a;
}
__device__ __forceinline__ unsigned ld_acq(const unsigned* p) {
    unsigned v;
    asm volatile("ld.acquire.gpu.global.u32 %0, [%1];" : "=r"(v) : "l"(p) : "memory");
    return v;
}
__device__ __forceinline__ void st_rel(unsigned* p, unsigned v) {
    asm volatile("st.release.gpu.global.u32 [%0], %1;" :: "l"(p), "r"(v) : "memory");
}

#define LDSM4(r0, r1, r2, r3, addr) \
    asm volatile("ldmatrix.sync.aligned.m8n8.x4.shared.b16 {%0,%1,%2,%3}, [%4];" \
        : "=r"(r0), "=r"(r1), "=r"(r2), "=r"(r3) : "r"(addr))

#define MMA(d, a, b0_, b1_) \
    asm volatile("mma.sync.aligned.m16n8k16.row.col.f32.f16.f16.f32 " \
        "{%0,%1,%2,%3}, {%4,%5,%6,%7}, {%8,%9}, {%0,%1,%2,%3};" \
        : "+f"((d)[0]), "+f"((d)[1]), "+f"((d)[2]), "+f"((d)[3]) \
        : "r"((a)[0]), "r"((a)[1]), "r"((a)[2]), "r"((a)[3]), "r"(b0_), "r"(b1_))

__device__ __forceinline__ void split16(float v, __half& hi, __half& lo) {
    hi = __float2half_rn(v);
    lo = __float2half_rn((v - __half2float(hi)) * SCALE_LO);
}
// B buffers: [n=batch 64][k 128] f16, row 256B, 16B-unit swizzle by (n&7)
__device__ __forceinline__ uint32_t b_off(int n, int kbyte) {
    return (uint32_t)n * 256u + ((uint32_t)kbyte ^ (((uint32_t)n & 7u) << 4));
}

__global__ void rnn_reset_kernel() {
    int i = threadIdx.x;
    if (i < NPAIRS) { g_prod[i] = 0u; g_cons[i] = 0u; }
}

__global__ __launch_bounds__(NTHREADS, 1)
void rnn_mma_kernel(const float* __restrict__ x,    const float* __restrict__ h0,
                    const float* __restrict__ Wi0,  const float* __restrict__ Wih,
                    const float* __restrict__ Whh,  const float* __restrict__ bih,
                    const float* __restrict__ bhh,  const float* __restrict__ Wout,
                    const float* __restrict__ bout, float* __restrict__ out)
{
    extern __shared__ __align__(128) unsigned char sm[];
    const uint32_t smb = smem_u32(sm);
    const int tid = threadIdx.x, warp = tid >> 5, lane = tid & 31;
    const int stage = blockIdx.x >> 3, chunk = blockIdx.x & 7;
    const int b0 = chunk * CHUNKB, l = stage;
    const bool first = (stage == 0), last = (stage == NSTAGES - 1);

    // ---- zero all smem ----
    for (int i = tid; i < SMEM_BYTES / 16; i += NTHREADS)
        ((float4*)sm)[i] = make_float4(0.f, 0.f, 0.f, 0.f);
    __syncthreads();

    // ---- A staging fill: [m 128][k 224] f16, I=k[0,112), H=k[112,224) ----
    __half* AHst = (__half*)(sm + S_A_HI);
    __half* ALst = (__half*)(sm + S_A_LO);
    if (first) {
        for (int idx = tid; idx < HID * HID; idx += NTHREADS) {
            int jj = idx / HID, kk = idx % HID;
            __half hi, lo; split16(Whh[idx], hi, lo);
            int o = jj * 224 + 112 + kk;
            AHst[o] = hi; ALst[o] = lo;
        }
        for (int jj = tid; jj < HID; jj += NTHREADS) {
            __half hi, lo; split16(Wi0[jj], hi, lo);
            AHst[jj * 224] = hi; ALst[jj * 224] = lo;   // x at k=0
        }
    } else {
        for (int idx = tid; idx < 2 * HID * HID; idx += NTHREADS) {
            int m = idx / (HID * HID), r = idx % (HID * HID);
            int jj = r / HID, kk = r % HID;
            float v = m ? Whh[(size_t)l * HID * HID + r] : Wih[(size_t)(l - 1) * HID * HID + r];
            __half hi, lo; split16(v, hi, lo);
            int o = jj * 224 + (m ? 112 + kk : kk);
            AHst[o] = hi; ALst[o] = lo;
        }
    }
    // ---- BH fill from h0 ----
    for (int idx = tid; idx < CHUNKB * HID; idx += NTHREADS) {
        int b = idx / HID, jj = idx % HID;
        __half hi, lo; split16(h0[((size_t)l * BATCH + b0 + b) * HID + jj], hi, lo);
        uint32_t o = b_off(b, 2 * jj);
        *(__half*)(sm + S_BH_HI + o) = hi;
        *(__half*)(sm + S_BH_LO + o) = lo;
    }
    __syncthreads();

    // ---- A fragments -> registers (warps 0..6) ----
    uint32_t AH[14][4], AL[14][4];
    if (warp < 7) {
#pragma unroll
        for (int ci = 0; ci < 14; ci++) {
            uint32_t r  = 16u * warp + (lane & 15);
            uint32_t kb = 32u * ci + (((uint32_t)(lane >> 4)) << 4);
            uint32_t a  = smb + S_A_HI + r * 448u + kb;
            LDSM4(AH[ci][0], AH[ci][1], AH[ci][2], AH[ci][3], a);
            LDSM4(AL[ci][0], AL[ci][1], AL[ci][2], AL[ci][3], a + 57344u);
        }
    }

    const int j0 = 16 * warp + (lane >> 2), j1 = j0 + 8;
    float bias0 = 0.f, bias1 = 0.f, w0 = 0.f, w1 = 0.f;
    if (warp < 7) {
        if (j0 < HID) bias0 = bih[l * HID + j0] + bhh[l * HID + j0];
        if (j1 < HID) bias1 = bih[l * HID + j1] + bhh[l * HID + j1];
        if (last) {
            if (j0 < HID) w0 = Wout[j0];
            if (j1 < HID) w1 = Wout[j1];
        }
    }
    const float boutv = bout[0];

    const int pc_in = (stage - 1) * NCHUNK + chunk, pc_out = stage * NCHUNK + chunk;
    unsigned char* ring_in  = g_ring + (size_t)pc_in  * RING_D * RING_SLOT;
    unsigned char* ring_out = g_ring + (size_t)pc_out * RING_D * RING_SLOT;

    float xv = 0.f;
    if (first && tid < CHUNKB) xv = x[(size_t)(b0 + tid) * TSTEPS];

    const uint32_t browoff = (uint32_t)(lane & 15) * 256u;
    const uint32_t bcol16  = ((uint32_t)(lane >> 4)) << 4;
    const uint32_t bswz    = ((uint32_t)(lane & 7)) << 4;
    float* sRed = (float*)(sm + S_RED);

    for (int t = 0; t < TSTEPS; t++) {
        // -------- phase 1: acquire input --------
        if (first) {
            if (tid < CHUNKB) {
                __half hi, lo; split16(xv, hi, lo);
                uint32_t o = b_off(tid, 0);
                *(__half*)(sm + S_BI_HI + o) = hi;
                *(__half*)(sm + S_BI_LO + o) = lo;
                if (t + 1 < TSTEPS) xv = x[(size_t)(b0 + tid) * TSTEPS + t + 1];
            }
            if (tid == 0 && t >= RING_D)
                while (ld_acq(&g_cons[pc_out]) < (unsigned)(t + 1 - RING_D)) {}
            __syncthreads();
        } else {
            if (tid == 0) {
                while (ld_acq(&g_prod[pc_in]) < (unsigned)(t + 1)) {}
                if (!last && t >= RING_D)
                    while (ld_acq(&g_cons[pc_out]) < (unsigned)(t + 1 - RING_D)) {}
            }
            __syncthreads();
            const float4* src = (const float4*)(ring_in + (size_t)(t & (RING_D - 1)) * RING_SLOT);
            float4* dst = (float4*)(sm + S_BI_HI);
#pragma unroll
            for (int i = 0; i < 8; i++) dst[tid + i * NTHREADS] = __ldcg(src + tid + i * NTHREADS);
            __syncthreads();
            if (tid == 0) st_rel(&g_cons[pc_in], (unsigned)(t + 1));
        }

        // -------- phase 2: MMA --------
        float acc1[8][4], acc2[8][4];
        if (warp < 7) {
#pragma unroll
            for (int nt = 0; nt < 8; nt++) {
                acc1[nt][0] = bias0; acc1[nt][1] = bias0;
                acc1[nt][2] = bias1; acc1[nt][3] = bias1;
                acc2[nt][0] = 0.f; acc2[nt][1] = 0.f; acc2[nt][2] = 0.f; acc2[nt][3] = 0.f;
            }
#pragma unroll
            for (int ci = 0; ci < 14; ci++) {
                if (first && ci >= 1 && ci < 7) continue;  // zero input chunks (only k=0 is live)
                uint32_t base = smb + ((ci < 7) ? S_BI_HI : S_BH_HI);
                uint32_t colx = ((32u * (uint32_t)((ci < 7) ? ci : ci - 7)) + bcol16) ^ bswz;
#pragma unroll
                for (int p = 0; p < 4; p++) {
                    uint32_t ab = base + ((uint32_t)p << 12) + browoff + colx;
                    uint32_t bh0, bh1, bh2, bh3, bl0, bl1, bl2, bl3;
                    LDSM4(bh0, bh1, bh2, bh3, ab);
                    LDSM4(bl0, bl1, bl2, bl3, ab + 16384u);
                    // B operand pairing: {k0-7, k8-15} of one n-block
                    MMA(acc1[2 * p],     AH[ci], bh0, bh2);
                    MMA(acc1[2 * p + 1], AH[ci], bh1, bh3);
                    MMA(acc2[2 * p],     AH[ci], bl0, bl2);
                    MMA(acc2[2 * p + 1], AH[ci], bl1, bl3);
                    MMA(acc2[2 * p],     AL[ci], bh0, bh2);
                    MMA(acc2[2 * p + 1], AL[ci], bh1, bh3);
                }
            }
        }
        __syncthreads();   // all BH reads complete before overwrite

        // -------- phase 3: epilogue --------
        if (warp < 7) {
            const uint32_t jb0 = 2u * (uint32_t)j0, jb1 = 2u * (uint32_t)j1;
#pragma unroll
            for (int nt = 0; nt < 8; nt++) {
                int c0 = nt * 8 + 2 * (lane & 3), c1 = c0 + 1;
                float v00 = acc1[nt][0] + acc2[nt][0] * INV_LO;
                float v01 = acc1[nt][1] + acc2[nt][1] * INV_LO;
                float v10 = acc1[nt][2] + acc2[nt][2] * INV_LO;
                float v11 = acc1[nt][3] + acc2[nt][3] * INV_LO;
                float h00 = tanhf(v00), h01 = tanhf(v01);
                float h10 = tanhf(v10), h11 = tanhf(v11);
                __half hi, lo;
                uint32_t o;
                o = b_off(c0, jb0); split16(h00, hi, lo);
                *(__half*)(sm + S_BH_HI + o) = hi; *(__half*)(sm + S_BH_LO + o) = lo;
                o = b_off(c1, jb0); split16(h01, hi, lo);
                *(__half*)(sm + S_BH_HI + o) = hi; *(__half*)(sm + S_BH_LO + o) = lo;
                o = b_off(c0, jb1); split16(h10, hi, lo);
                *(__half*)(sm + S_BH_HI + o) = hi; *(__half*)(sm + S_BH_LO + o) = lo;
                o = b_off(c1, jb1); split16(h11, hi, lo);
                *(__half*)(sm + S_BH_HI + o) = hi; *(__half*)(sm + S_BH_LO + o) = lo;
                if (last) {
                    float p0 = h00 * w0 + h10 * w1;
                    float p1 = h01 * w0 + h11 * w1;
#pragma unroll
                    for (int d = 4; d < 32; d <<= 1) {
                        p0 += __shfl_xor_sync(0xFFFFFFFFu, p0, d);
                        p1 += __shfl_xor_sync(0xFFFFFFFFu, p1, d);
                    }
                    if (lane < 4) {
                        sRed[warp * 64 + c0] = p0;
                        sRed[warp * 64 + c1] = p1;
                    }
                }
            }
        }
        __syncthreads();   // BH (and sRed) complete

        if (!last) {
            float4* dst = (float4*)(ring_out + (size_t)(t & (RING_D - 1)) * RING_SLOT);
            const float4* src = (const float4*)(sm + S_BH_HI);
#pragma unroll
            for (int i = 0; i < 8; i++) dst[tid + i * NTHREADS] = src[tid + i * NTHREADS];
            __syncthreads();
            if (tid == 0) st_rel(&g_prod[pc_out], (unsigned)(t + 1));
        } else {
            if (tid < CHUNKB) {
                float s = boutv;
#pragma unroll
                for (int w = 0; w < 7; w++) s += sRed[w * 64 + tid];
                out[(size_t)(b0 + tid) * TSTEPS + t] = s;
            }
        }
    }

    // ---- final hidden state ----
    __syncthreads();
    for (int idx = tid; idx < CHUNKB * HID; idx += NTHREADS) {
        int b = idx / HID, jj = idx % HID;
        uint32_t o = b_off(b, 2 * jj);
        float v = __half2float(*(const __half*)(sm + S_BH_HI + o))
                + __half2float(*(const __half*)(sm + S_BH_LO + o)) * INV_LO;
        out[(size_t)BATCH * TSTEPS + ((size_t)l * BATCH + b0 + b) * HID + jj] = v;
    }
}

extern "C" void kernel_launch(void* const* d_in, const int* in_sizes, int n_in,
                              void* d_out, int out_size) {
    const float* x    = (const float*)d_in[0];
    const float* h0   = (const float*)d_in[1];
    const float* Wi0  = (const float*)d_in[2];
    const float* Wih  = (const float*)d_in[3];
    const float* Whh  = (const float*)d_in[4];
    const float* bih  = (const float*)d_in[5];
    const float* bhh  = (const float*)d_in[6];
    const float* Wout = (const float*)d_in[7];
    const float* bout = (const float*)d_in[8];
    float* out = (float*)d_out;

    cudaFuncSetAttribute(rnn_mma_kernel, cudaFuncAttributeMaxDynamicSharedMemorySize, SMEM_BYTES);
    rnn_reset_kernel<<<1, 256>>>();
    rnn_mma_kernel<<<NSTAGES * NCHUNK, NTHREADS, SMEM_BYTES>>>(
        x, h0, Wi0, Wih, Whh, bih, bhh, Wout, bout, out);
}

// round 8
// speedup vs baseline: 2.0428x; 1.1305x over previous
#include <cuda_runtime.h>
#include <cuda_fp16.h>
#include <cstdint>

#define HID      100
#define BATCH    512
#define TSTEPS   512
#define NCHUNK   8
#define CHUNKB   64
#define NSTAGES  10
#define NTHREADS 256
#define RING_D   4
#define NPAIRS   ((NSTAGES-1)*NCHUNK)   // 72

#define SCALE_LO 2048.0f
#define INV_LO   (1.0f/2048.0f)
#define APITCH   464                    // A row pitch (bytes): conflict-free ldmatrix phases

// ---- smem byte offsets ----
#define S_RED    0                       // 2048
#define S_BI_HI  2048                    // B input region  [64][128] f16 = 16KB
#define S_BI_LO  (S_BI_HI + 16384)
#define S_BH_HI  (S_BI_LO + 16384)       // B hidden region [64][128] f16
#define S_BH_LO  (S_BH_HI + 16384)
#define S_A_HI   (S_BH_LO + 16384)       // A [128 rows][224 k] f16, pitch 464B
#define S_A_LO   (S_A_HI + 128*APITCH)
#define SMEM_BYTES (S_A_LO + 128*APITCH) // 186368

#define RING_SLOT 32768
__device__ unsigned char g_ring[(size_t)NPAIRS * RING_D * RING_SLOT];
__device__ unsigned g_prod[NPAIRS];
__device__ unsigned g_cons[NPAIRS];

__device__ __forceinline__ uint32_t smem_u32(const void* p) {
    uint32_t a;
    asm("{ .reg .u64 t; cvta.to.shared.u64 t, %1; cvt.u32.u64 %0, t; }" : "=r"(a) : "l"(p));
    return a;
}
__device__ __forceinline__ unsigned ld_acq(const unsigned* p) {
    unsigned v;
    asm volatile("ld.acquire.gpu.global.u32 %0, [%1];" : "=r"(v) : "l"(p) : "memory");
    return v;
}
__device__ __forceinline__ void st_rel(unsigned* p, unsigned v) {
    asm volatile("st.release.gpu.global.u32 [%0], %1;" :: "l"(p), "r"(v) : "memory");
}

#define LDSM4(r0, r1, r2, r3, addr) \
    asm volatile("ldmatrix.sync.aligned.m8n8.x4.shared.b16 {%0,%1,%2,%3}, [%4];" \
        : "=r"(r0), "=r"(r1), "=r"(r2), "=r"(r3) : "r"(addr))

#define MMA(d, a0_, a1_, a2_, a3_, b0_, b1_) \
    asm volatile("mma.sync.aligned.m16n8k16.row.col.f32.f16.f16.f32 " \
        "{%0,%1,%2,%3}, {%4,%5,%6,%7}, {%8,%9}, {%0,%1,%2,%3};" \
        : "+f"((d)[0]), "+f"((d)[1]), "+f"((d)[2]), "+f"((d)[3]) \
        : "r"(a0_), "r"(a1_), "r"(a2_), "r"(a3_), "r"(b0_), "r"(b1_))

__device__ __forceinline__ void split16(float v, __half& hi, __half& lo) {
    hi = __float2half_rn(v);
    lo = __float2half_rn((v - __half2float(hi)) * SCALE_LO);
}
__device__ __forceinline__ float fast_tanh(float x) {
    float e, r;
    asm("ex2.approx.f32 %0, %1;" : "=f"(e) : "f"(x * 2.8853900817779268f)); // 2*log2(e)
    asm("rcp.approx.f32 %0, %1;" : "=f"(r) : "f"(e + 1.0f));
    return fmaf(-2.0f, r, 1.0f);
}
// B buffers: [n 64][k 128] f16, row 256B, 16B-unit swizzle by (n&7)
__device__ __forceinline__ uint32_t b_off(int n, int kbyte) {
    return (uint32_t)n * 256u + ((uint32_t)kbyte ^ (((uint32_t)n & 7u) << 4));
}

__global__ void rnn_reset_kernel() {
    int i = threadIdx.x;
    if (i < NPAIRS) { g_prod[i] = 0u; g_cons[i] = 0u; }
}

__global__ __launch_bounds__(NTHREADS, 1)
void rnn_mma_kernel(const float* __restrict__ x,    const float* __restrict__ h0,
                    const float* __restrict__ Wi0,  const float* __restrict__ Wih,
                    const float* __restrict__ Whh,  const float* __restrict__ bih,
                    const float* __restrict__ bhh,  const float* __restrict__ Wout,
                    const float* __restrict__ bout, float* __restrict__ out)
{
    extern __shared__ __align__(128) unsigned char sm[];
    const uint32_t smb = smem_u32(sm);
    const int tid = threadIdx.x, warp = tid >> 5, lane = tid & 31;
    const int stage = blockIdx.x >> 3, chunk = blockIdx.x & 7;
    const int b0 = chunk * CHUNKB, l = stage;
    const bool first = (stage == 0), last = (stage == NSTAGES - 1);

    // ---- zero all smem ----
    for (int i = tid; i < SMEM_BYTES / 16; i += NTHREADS)
        ((float4*)sm)[i] = make_float4(0.f, 0.f, 0.f, 0.f);
    __syncthreads();

    // ---- A fill: [m 128][k 224] f16, pitch 464B. I=k[0,112), H=k[112,224) ----
    if (first) {
        for (int idx = tid; idx < HID * HID; idx += NTHREADS) {
            int jj = idx / HID, kk = idx % HID;
            __half hi, lo; split16(Whh[idx], hi, lo);
            uint32_t o = (uint32_t)jj * APITCH + 2u * (112 + kk);
            *(__half*)(sm + S_A_HI + o) = hi; *(__half*)(sm + S_A_LO + o) = lo;
        }
        for (int jj = tid; jj < HID; jj += NTHREADS) {
            __half hi, lo; split16(Wi0[jj], hi, lo);
            uint32_t o = (uint32_t)jj * APITCH;              // x at k=0
            *(__half*)(sm + S_A_HI + o) = hi; *(__half*)(sm + S_A_LO + o) = lo;
        }
    } else {
        for (int idx = tid; idx < 2 * HID * HID; idx += NTHREADS) {
            int m = idx / (HID * HID), r = idx % (HID * HID);
            int jj = r / HID, kk = r % HID;
            float v = m ? Whh[(size_t)l * HID * HID + r] : Wih[(size_t)(l - 1) * HID * HID + r];
            __half hi, lo; split16(v, hi, lo);
            uint32_t o = (uint32_t)jj * APITCH + 2u * (m ? 112 + kk : kk);
            *(__half*)(sm + S_A_HI + o) = hi; *(__half*)(sm + S_A_LO + o) = lo;
        }
    }
    // ---- BH fill from h0 ----
    for (int idx = tid; idx < CHUNKB * HID; idx += NTHREADS) {
        int b = idx / HID, jj = idx % HID;
        __half hi, lo; split16(h0[((size_t)l * BATCH + b0 + b) * HID + jj], hi, lo);
        uint32_t o = b_off(b, 2 * jj);
        *(__half*)(sm + S_BH_HI + o) = hi;
        *(__half*)(sm + S_BH_LO + o) = lo;
    }
    __syncthreads();

    // ---- A-hi fragments -> registers (warps 0..6); A-lo streamed per step ----
    const uint32_t aRow = 16u * (uint32_t)warp + (uint32_t)(lane & 15);
    const uint32_t aCol = ((uint32_t)(lane >> 4)) << 4;
    const uint32_t aHiBase = smb + S_A_HI + aRow * APITCH + aCol;
    const uint32_t aLoBase = smb + S_A_LO + aRow * APITCH + aCol;
    uint32_t AH[14][4];
    if (warp < 7) {
#pragma unroll
        for (int ci = 0; ci < 14; ci++)
            LDSM4(AH[ci][0], AH[ci][1], AH[ci][2], AH[ci][3], aHiBase + 32u * ci);
    }

    const int j0 = 16 * warp + (lane >> 2), j1 = j0 + 8;
    float bias0 = 0.f, bias1 = 0.f, w0 = 0.f, w1 = 0.f;
    if (warp < 7) {
        if (j0 < HID) bias0 = bih[l * HID + j0] + bhh[l * HID + j0];
        if (j1 < HID) bias1 = bih[l * HID + j1] + bhh[l * HID + j1];
        if (last) {
            if (j0 < HID) w0 = Wout[j0];
            if (j1 < HID) w1 = Wout[j1];
        }
    }
    const float boutv = bout[0];

    const int pc_in = (stage - 1) * NCHUNK + chunk, pc_out = stage * NCHUNK + chunk;
    unsigned char* ring_in  = g_ring + (size_t)pc_in  * RING_D * RING_SLOT;
    unsigned char* ring_out = g_ring + (size_t)pc_out * RING_D * RING_SLOT;

    float xv = 0.f;
    if (first && tid < CHUNKB) xv = x[(size_t)(b0 + tid) * TSTEPS];

    const uint32_t browoff = (uint32_t)(lane & 15) * 256u;
    const uint32_t bcol16  = ((uint32_t)(lane >> 4)) << 4;
    const uint32_t bswz    = ((uint32_t)(lane & 7)) << 4;
    float* sRed = (float*)(sm + S_RED);

    // epilogue store offsets (constant per thread): nt adds nt*2048
    const int ec0 = 2 * (lane & 3), ec1 = ec0 + 1;
    const uint32_t o00 = b_off(ec0, 2 * j0), o01 = b_off(ec1, 2 * j0);
    const uint32_t o10 = b_off(ec0, 2 * j1), o11 = b_off(ec1, 2 * j1);

    for (int t = 0; t < TSTEPS; t++) {
        // -------- phase 0: poll + prefetch ring into regs (stage>0) --------
        float4 pf[8];
        if (first) {
            if (tid < CHUNKB) {
                __half hi, lo; split16(xv, hi, lo);
                uint32_t o = b_off(tid, 0);
                *(__half*)(sm + S_BI_HI + o) = hi;
                *(__half*)(sm + S_BI_LO + o) = lo;
                if (t + 1 < TSTEPS) xv = x[(size_t)(b0 + tid) * TSTEPS + t + 1];
            }
        } else {
            while (ld_acq(&g_prod[pc_in]) < (unsigned)(t + 1)) {}
            const float4* src = (const float4*)(ring_in + (size_t)(t & (RING_D - 1)) * RING_SLOT);
#pragma unroll
            for (int i = 0; i < 8; i++) pf[i] = __ldcg(src + tid + i * NTHREADS);
        }

        // -------- phase 1: hidden-part MMA (ci 7..13) --------
        float acc1[8][4], acc2[8][4];
        if (warp < 7) {
#pragma unroll
            for (int nt = 0; nt < 8; nt++) {
                acc1[nt][0] = bias0; acc1[nt][1] = bias0;
                acc1[nt][2] = bias1; acc1[nt][3] = bias1;
                acc2[nt][0] = 0.f; acc2[nt][1] = 0.f; acc2[nt][2] = 0.f; acc2[nt][3] = 0.f;
            }
#pragma unroll
            for (int ci = 7; ci < 14; ci++) {
                uint32_t AL0, AL1, AL2, AL3;
                LDSM4(AL0, AL1, AL2, AL3, aLoBase + 32u * ci);
                uint32_t colx = ((32u * (uint32_t)(ci - 7)) + bcol16) ^ bswz;
#pragma unroll
                for (int p = 0; p < 4; p++) {
                    uint32_t ab = smb + S_BH_HI + ((uint32_t)p << 12) + browoff + colx;
                    uint32_t bh0, bh1, bh2, bh3, bl0, bl1, bl2, bl3;
                    LDSM4(bh0, bh1, bh2, bh3, ab);
                    LDSM4(bl0, bl1, bl2, bl3, ab + 16384u);
                    MMA(acc1[2 * p],     AH[ci][0], AH[ci][1], AH[ci][2], AH[ci][3], bh0, bh2);
                    MMA(acc1[2 * p + 1], AH[ci][0], AH[ci][1], AH[ci][2], AH[ci][3], bh1, bh3);
                    MMA(acc2[2 * p],     AH[ci][0], AH[ci][1], AH[ci][2], AH[ci][3], bl0, bl2);
                    MMA(acc2[2 * p + 1], AH[ci][0], AH[ci][1], AH[ci][2], AH[ci][3], bl1, bl3);
                    MMA(acc2[2 * p],     AL0, AL1, AL2, AL3, bh0, bh2);
                    MMA(acc2[2 * p + 1], AL0, AL1, AL2, AL3, bh1, bh3);
                }
            }
        }

        // -------- phase 2: stage input, sync --------
        if (!first) {
            float4* dst = (float4*)(sm + S_BI_HI);
#pragma unroll
            for (int i = 0; i < 8; i++) dst[tid + i * NTHREADS] = pf[i];
        }
        __syncthreads();   // input staged; all BH reads (phase 1) complete
        if (!first && tid == 0) st_rel(&g_cons[pc_in], (unsigned)(t + 1));

        // -------- phase 3: input-part MMA (ci 0..6; stage0: ci 0 only) --------
        if (warp < 7) {
#pragma unroll
            for (int ci = 0; ci < 7; ci++) {
                if (first && ci >= 1) break;
                uint32_t AL0, AL1, AL2, AL3;
                LDSM4(AL0, AL1, AL2, AL3, aLoBase + 32u * ci);
                uint32_t colx = ((32u * (uint32_t)ci) + bcol16) ^ bswz;
#pragma unroll
                for (int p = 0; p < 4; p++) {
                    uint32_t ab = smb + S_BI_HI + ((uint32_t)p << 12) + browoff + colx;
                    uint32_t bh0, bh1, bh2, bh3, bl0, bl1, bl2, bl3;
                    LDSM4(bh0, bh1, bh2, bh3, ab);
                    LDSM4(bl0, bl1, bl2, bl3, ab + 16384u);
                    MMA(acc1[2 * p],     AH[ci][0], AH[ci][1], AH[ci][2], AH[ci][3], bh0, bh2);
                    MMA(acc1[2 * p + 1], AH[ci][0], AH[ci][1], AH[ci][2], AH[ci][3], bh1, bh3);
                    MMA(acc2[2 * p],     AH[ci][0], AH[ci][1], AH[ci][2], AH[ci][3], bl0, bl2);
                    MMA(acc2[2 * p + 1], AH[ci][0], AH[ci][1], AH[ci][2], AH[ci][3], bl1, bl3);
                    MMA(acc2[2 * p],     AL0, AL1, AL2, AL3, bh0, bh2);
                    MMA(acc2[2 * p + 1], AL0, AL1, AL2, AL3, bh1, bh3);
                }
            }

            // -------- phase 4: epilogue --------
#pragma unroll
            for (int nt = 0; nt < 8; nt++) {
                const uint32_t ntoff = (uint32_t)nt << 11;
                float h00 = fast_tanh(fmaf(acc2[nt][0], INV_LO, acc1[nt][0]));
                float h01 = fast_tanh(fmaf(acc2[nt][1], INV_LO, acc1[nt][1]));
                float h10 = fast_tanh(fmaf(acc2[nt][2], INV_LO, acc1[nt][2]));
                float h11 = fast_tanh(fmaf(acc2[nt][3], INV_LO, acc1[nt][3]));
                __half hi, lo;
                split16(h00, hi, lo);
                *(__half*)(sm + S_BH_HI + o00 + ntoff) = hi; *(__half*)(sm + S_BH_LO + o00 + ntoff) = lo;
                split16(h01, hi, lo);
                *(__half*)(sm + S_BH_HI + o01 + ntoff) = hi; *(__half*)(sm + S_BH_LO + o01 + ntoff) = lo;
                split16(h10, hi, lo);
                *(__half*)(sm + S_BH_HI + o10 + ntoff) = hi; *(__half*)(sm + S_BH_LO + o10 + ntoff) = lo;
                split16(h11, hi, lo);
                *(__half*)(sm + S_BH_HI + o11 + ntoff) = hi; *(__half*)(sm + S_BH_LO + o11 + ntoff) = lo;
                if (last) {
                    float p0 = h00 * w0 + h10 * w1;
                    float p1 = h01 * w0 + h11 * w1;
#pragma unroll
                    for (int d = 4; d < 32; d <<= 1) {
                        p0 += __shfl_xor_sync(0xFFFFFFFFu, p0, d);
                        p1 += __shfl_xor_sync(0xFFFFFFFFu, p1, d);
                    }
                    if (lane < 4) {
                        sRed[warp * 64 + nt * 8 + ec0] = p0;
                        sRed[warp * 64 + nt * 8 + ec1] = p1;
                    }
                }
            }
        }
        // backpressure poll before copy-out
        if (!last && t >= RING_D)
            while (ld_acq(&g_cons[pc_out]) < (unsigned)(t + 1 - RING_D)) {}
        __syncthreads();   // BH (and sRed) writes complete

        if (!last) {
            float4* dst = (float4*)(ring_out + (size_t)(t & (RING_D - 1)) * RING_SLOT);
            const float4* src = (const float4*)(sm + S_BH_HI);
#pragma unroll
            for (int i = 0; i < 8; i++) dst[tid + i * NTHREADS] = src[tid + i * NTHREADS];
            __syncthreads();
            if (tid == 0) st_rel(&g_prod[pc_out], (unsigned)(t + 1));
        } else {
            if (tid < CHUNKB) {
                float s = boutv;
#pragma unroll
                for (int w = 0; w < 7; w++) s += sRed[w * 64 + tid];
                out[(size_t)(b0 + tid) * TSTEPS + t] = s;
            }
            __syncthreads();
        }
    }

    // ---- final hidden state ----
    for (int idx = tid; idx < CHUNKB * HID; idx += NTHREADS) {
        int b = idx / HID, jj = idx % HID;
        uint32_t o = b_off(b, 2 * jj);
        float v = __half2float(*(const __half*)(sm + S_BH_HI + o))
                + __half2float(*(const __half*)(sm + S_BH_LO + o)) * INV_LO;
        out[(size_t)BATCH * TSTEPS + ((size_t)l * BATCH + b0 + b) * HID + jj] = v;
    }
}

extern "C" void kernel_launch(void* const* d_in, const int* in_sizes, int n_in,
                              void* d_out, int out_size) {
    const float* x    = (const float*)d_in[0];
    const float* h0   = (const float*)d_in[1];
    const float* Wi0  = (const float*)d_in[2];
    const float* Wih  = (const float*)d_in[3];
    const float* Whh  = (const float*)d_in[4];
    const float* bih  = (const float*)d_in[5];
    const float* bhh  = (const float*)d_in[6];
    const float* Wout = (const float*)d_in[7];
    const float* bout = (const float*)d_in[8];
    float* out = (float*)d_out;

    cudaFuncSetAttribute(rnn_mma_kernel, cudaFuncAttributeMaxDynamicSharedMemorySize, SMEM_BYTES);
    rnn_reset_kernel<<<1, 256>>>();
    rnn_mma_kernel<<<NSTAGES * NCHUNK, NTHREADS, SMEM_BYTES>>>(
        x, h0, Wi0, Wih, Whh, bih, bhh, Wout, bout, out);
}